// round 10
// baseline (speedup 1.0000x reference)
#include <cuda_runtime.h>
#include <math.h>

#define NS 512       // sequence length N
#define DD 64        // feature dim d
#define NB 64        // batch B
#define NCT 128      // column tiles (4 wide each)
#define NSTEP 159    // 128 column tiles + 31 lane skew
#define DEADC (-20000)
#define SENTV (-2147483647 - 1)   // INT_MIN marker = "not yet written"

// 64 MB scratch: E[b,i,j] = exp(-||x_i - y_j||)
__device__ float g_E[(size_t)NB * NS * NS];

// ---------------------------------------------------------------------------
// Packed f32x2 FMA (Blackwell)
// ---------------------------------------------------------------------------
__device__ __forceinline__ void fma2(unsigned long long& d,
                                     unsigned long long a,
                                     unsigned long long b) {
    asm("fma.rn.f32x2 %0, %1, %2, %0;" : "+l"(d) : "l"(a), "l"(b));
}

// ---------------------------------------------------------------------------
// Stage 1: E[b,i,j] = exp(-sqrt(max(0, |x_i|^2 + |y_j|^2 - 2 x_i.y_j)))
// (unchanged — ~65us)
// ---------------------------------------------------------------------------
__global__ void __launch_bounds__(256, 2)
cdist_kernel(const float* __restrict__ X, const float* __restrict__ Y) {
    __shared__ float Xs[64 * 64];
    __shared__ float Ys[64 * 64];
    __shared__ float xn[64], yn[64];

    const int b  = blockIdx.z;
    const int i0 = blockIdx.y * 64;
    const int j0 = blockIdx.x * 64;
    const int tid = threadIdx.y * 16 + threadIdx.x;

    const float* Xg = X + ((size_t)b * NS + i0) * DD;
    const float* Yg = Y + ((size_t)b * NS + j0) * DD;

    float4* Xs4 = reinterpret_cast<float4*>(Xs);
    float4* Ys4 = reinterpret_cast<float4*>(Ys);

#pragma unroll
    for (int t = 0; t < 4; ++t) {
        int lin = t * 256 + tid;
        int row = lin >> 4;
        int k4  = lin & 15;
        int sw  = k4 ^ (row & 15);
        Xs4[row * 16 + sw] = *reinterpret_cast<const float4*>(Xg + row * DD + k4 * 4);
        Ys4[row * 16 + sw] = *reinterpret_cast<const float4*>(Yg + row * DD + k4 * 4);
    }
    __syncthreads();

    if (tid < 128) {
        int r = tid & 63;
        const float4* P = (tid < 64) ? reinterpret_cast<const float4*>(Xs)
                                     : reinterpret_cast<const float4*>(Ys);
        float s = 0.0f;
#pragma unroll
        for (int k4 = 0; k4 < 16; ++k4) {
            float4 v = P[r * 16 + (k4 ^ (r & 15))];
            s += v.x * v.x + v.y * v.y + v.z * v.z + v.w * v.w;
        }
        if (tid < 64) xn[r] = s; else yn[r] = s;
    }
    __syncthreads();

    const int tx = threadIdx.x, ty = threadIdx.y;

    unsigned long long acc[4][4];
#pragma unroll
    for (int r = 0; r < 4; ++r)
#pragma unroll
        for (int c = 0; c < 4; ++c) acc[r][c] = 0ull;

    const ulonglong2* Xs2 = reinterpret_cast<const ulonglong2*>(Xs);
    const ulonglong2* Ys2 = reinterpret_cast<const ulonglong2*>(Ys);

#pragma unroll
    for (int k4 = 0; k4 < 16; ++k4) {
        ulonglong2 av[4], bv[4];
#pragma unroll
        for (int r = 0; r < 4; ++r) {
            int i = ty + 16 * r;
            av[r] = Xs2[i * 16 + (k4 ^ (i & 15))];
        }
#pragma unroll
        for (int c = 0; c < 4; ++c) {
            int j = tx + 16 * c;
            bv[c] = Ys2[j * 16 + (k4 ^ (j & 15))];
        }
#pragma unroll
        for (int r = 0; r < 4; ++r)
#pragma unroll
            for (int c = 0; c < 4; ++c) {
                fma2(acc[r][c], av[r].x, bv[c].x);
                fma2(acc[r][c], av[r].y, bv[c].y);
            }
    }

    float* Eout = g_E + (size_t)b * NS * NS;
#pragma unroll
    for (int r = 0; r < 4; ++r) {
        int i = ty + 16 * r;
#pragma unroll
        for (int c = 0; c < 4; ++c) {
            int j = tx + 16 * c;
            float lo = __uint_as_float((unsigned)(acc[r][c] & 0xffffffffull));
            float hi = __uint_as_float((unsigned)(acc[r][c] >> 32));
            float d2 = xn[i] + yn[j] - 2.0f * (lo + hi);
            float dist = sqrtf(fmaxf(d2, 0.0f));
            Eout[(size_t)(i0 + i) * NS + (j0 + j)] =
                exp2f(-1.4426950408889634f * dist);
        }
    }
}

// ---------------------------------------------------------------------------
// Stage 2: weight-domain soft-DTW, binary scaling, BARRIER-FREE systolic.
// 64 CTAs x 128 threads. Warp w owns a 128-row band; lane l owns 4 rows.
// At warp-step s, lane l computes the 4x4 tile at column-tile ct = s - l.
// Top frontier: __shfl_up from lane l-1 (previous step). Warp boundaries:
// SMEM mailbox with 31-step structural slack (consumer's slot was produced
// 31 producer-steps earlier -> no steady-state spinning).
// ---------------------------------------------------------------------------
__device__ __forceinline__ float exp2i_neg(int e) {
    return (e >= -126) ? __int_as_float((e + 127) << 23) : 0.0f;
}
__device__ __forceinline__ int fexp(float m) {
    return ((__float_as_int(m) >> 23) & 0xff) - 127;
}

struct TS {
    float l0, l1, l2, l3;   // left frontier (renormed)
    int leftC2;
    float cornE;            // corner (own exponent)
    int cornC2;
};

// One 4x4 tile. top = (t, sTop); E rows in cb[4] (float4 = 4 cols).
// Outputs: o (renormed bottom row), oC2; updates st (left/corner).
__device__ __forceinline__ void subtile4(
    int ct, int tileRow, float4 t, int sTop,
    const float4 (&cb)[4], TS& st, float4& o, int& oC2)
{
    const bool rst = (ct == 0);
    float L0 = rst ? 0.0f : st.l0;
    float L1 = rst ? 0.0f : st.l1;
    float L2 = rst ? 0.0f : st.l2;
    float L3 = rst ? 0.0f : st.l3;
    int   LC = rst ? DEADC : st.leftC2;
    float CE = rst ? ((tileRow == 0) ? 1.0f : 0.0f) : st.cornE;
    int   CC = rst ? ((tileRow == 0) ? 0 : DEADC) : st.cornC2;

    int c2 = max(max(sTop, CC), LC);
    const float ft = exp2i_neg(sTop - c2);
    const float fc = exp2i_neg(CC   - c2);
    const float fl = exp2i_neg(LC   - c2);

    float prev[5];
    prev[0] = CE * fc;
    prev[1] = t.x * ft; prev[2] = t.y * ft; prev[3] = t.z * ft; prev[4] = t.w * ft;
    float lE0 = L0 * fl, lE1 = L1 * fl, lE2 = L2 * fl, lE3 = L3 * fl;
    const float newCorn = prev[4];

    float right[4];
#pragma unroll
    for (int a = 0; a < 4; ++a) {
        const float4 e = cb[a];
        const float nl = (a == 0) ? lE0 : (a == 1) ? lE1 : (a == 2) ? lE2 : lE3;
        float carry = prev[0];
        prev[0] = nl;
        float s;
        s = (carry + prev[1]) + prev[0]; carry = prev[1]; prev[1] = e.x * s;
        s = (carry + prev[2]) + prev[1]; carry = prev[2]; prev[2] = e.y * s;
        s = (carry + prev[3]) + prev[2]; carry = prev[3]; prev[3] = e.z * s;
        s = (carry + prev[4]) + prev[3];                  prev[4] = e.w * s;
        right[a] = prev[4];
    }

    // Merged renorm of the 8 outputs (span <= 3 cells: safe).
    float m = fmaxf(fmaxf(prev[1], prev[2]), fmaxf(prev[3], prev[4]));
    m = fmaxf(m, fmaxf(fmaxf(right[0], right[1]), fmaxf(right[2], right[3])));
    int em = fexp(m);
    float rs = __int_as_float((127 - em) << 23);
    int c2n = (m > 0.0f) ? (c2 + em) : DEADC;

    o = make_float4(prev[1] * rs, prev[2] * rs, prev[3] * rs, prev[4] * rs);
    oC2 = c2n;
    st.l0 = right[0] * rs; st.l1 = right[1] * rs;
    st.l2 = right[2] * rs; st.l3 = right[3] * rs;
    st.leftC2 = c2n;

    int ec = fexp(newCorn);
    st.cornE  = newCorn * __int_as_float((127 - ec) << 23);
    st.cornC2 = (newCorn > 0.0f) ? (c2 + ec) : DEADC;
}

__global__ void __launch_bounds__(128, 1)
dp_kernel(float* __restrict__ out) {
    const int b = blockIdx.x;
    const float* Eb = g_E + (size_t)b * NS * NS;

    __shared__ __align__(16) float4 mboxV[3][NCT];
    __shared__ int mboxM[3][NCT];

    const int tid = threadIdx.x;
    const int w = tid >> 5, l = tid & 31;
    const int tileRow = w * 32 + l;                 // 0..127
    const float* Erow = Eb + (size_t)(tileRow * 4) * NS;

    // Init mailbox markers to sentinel.
    for (int s = tid; s < 3 * NCT; s += 128) (&mboxM[0][0])[s] = SENTV;
    __syncthreads();   // the only barrier

    // Double-buffered E tile (4 rows x 4 cols = 4 x float4).
    float4 buf0[4], buf1[4];
#pragma unroll
    for (int a = 0; a < 4; ++a)
        buf0[a] = *reinterpret_cast<const float4*>(Erow + a * NS);   // ct = 0
#pragma unroll
    for (int a = 0; a < 4; ++a) buf1[a] = buf0[a];

    TS st;
    st.l0 = st.l1 = st.l2 = st.l3 = 0.f;
    st.leftC2 = DEADC; st.cornE = 0.f; st.cornC2 = DEADC;

    float4 pO = make_float4(0.f, 0.f, 0.f, 0.f);   // previous-step output
    int pC2 = DEADC;

    for (int s = 0; s < NSTEP; ++s) {
        const int ct = s - l;
        const bool act = (unsigned)ct < (unsigned)NCT;

        // Top frontier: lane l-1's previous-step output (warp-synchronous).
        float4 t;
        t.x = __shfl_up_sync(0xffffffffu, pO.x, 1);
        t.y = __shfl_up_sync(0xffffffffu, pO.y, 1);
        t.z = __shfl_up_sync(0xffffffffu, pO.z, 1);
        t.w = __shfl_up_sync(0xffffffffu, pO.w, 1);
        int tc = __shfl_up_sync(0xffffffffu, pC2, 1);

        if (l == 0) {
            if (w == 0 || !act) {
                t = make_float4(0.f, 0.f, 0.f, 0.f);
                tc = DEADC;
            } else {
                // Mailbox read: slot was produced 31 producer-steps ago ->
                // after the initial lag stabilizes, this never spins.
                unsigned addr =
                    (unsigned)__cvta_generic_to_shared(&mboxM[w - 1][ct]);
                int m;
                do {
                    asm volatile("ld.acquire.cta.shared.s32 %0, [%1];"
                                 : "=r"(m) : "r"(addr) : "memory");
                } while (m == SENTV);
                tc = m;
                t = mboxV[w - 1][ct];
            }
        }

        // Prefetch next step's E tile into the other buffer (clamped).
        {
            int ctn = ct + 1;
            ctn = (ctn < 0) ? 0 : (ctn > NCT - 1 ? NCT - 1 : ctn);
            const float* p = Erow + 4 * ctn;
            float4* nb = (s & 1) ? buf0 : buf1;
#pragma unroll
            for (int a = 0; a < 4; ++a)
                nb[a] = *reinterpret_cast<const float4*>(p + a * NS);
        }
        const float4(&cb)[4] = (s & 1) ? buf1 : buf0;

        float4 o; int oC2;
        subtile4(ct, tileRow, t, tc, cb, st, o, oC2);
        pO = o; pC2 = oC2;

        // Boundary producer: lane 31 of warps 0..2 publishes (one-shot slot).
        if (l == 31 && w < 3 && act) {
            mboxV[w][ct] = o;
            unsigned addr = (unsigned)__cvta_generic_to_shared(&mboxM[w][ct]);
            asm volatile("st.release.cta.shared.s32 [%0], %1;"
                         :: "r"(addr), "r"(oC2) : "memory");
        }

        // Final DP cell: tileRow 127 (w=3, l=31), ct = 127.
        if (w == 3 && l == 31 && ct == NCT - 1)
            out[b] = -(log2f(o.w) + (float)oC2) * 0.69314718055994530942f;
    }
}

// ---------------------------------------------------------------------------
extern "C" void kernel_launch(void* const* d_in, const int* in_sizes, int n_in,
                              void* d_out, int out_size) {
    (void)in_sizes; (void)n_in; (void)out_size;
    const float* X = (const float*)d_in[0];
    const float* Y = (const float*)d_in[1];
    float* out = (float*)d_out;

    dim3 g1(NS / 64, NS / 64, NB);   // (8, 8, 64)
    dim3 b1(16, 16);
    cdist_kernel<<<g1, b1>>>(X, Y);

    dp_kernel<<<NB, 128>>>(out);
}

// round 12
// speedup vs baseline: 3.1406x; 3.1406x over previous
#include <cuda_runtime.h>
#include <cuda_bf16.h>
#include <cstdint>

#define NS 512       // sequence length N
#define DD 64        // feature dim d
#define NB 64        // batch B
#define GTJ 64       // column tiles (8 wide each)
#define NDIAG 192    // 128 + 64 - 1 = 191, padded even
#define C2_NEG (-0x40000000)
#define PADF 4096    // guard pad (floats) around g_E for clamp-free prefetch
#define SLOT_OFF 256 // frontier slot offset so tj in [-127,191] maps in-bounds
#define SLOTS 640
#define L2E 1.4426950408889634f

// Guarded 64MB scratch: E[b,i,j] = exp(-||x_i - y_j||)
__device__ float g_Ebuf[(size_t)PADF + (size_t)NB * NS * NS + PADF];
// bf16-packed operands (u32 = 2 bf16, k-contiguous) + fp32 row norms
__device__ uint32_t g_Xbf[(size_t)NB * NS * (DD / 2)];
__device__ uint32_t g_Ybf[(size_t)NB * NS * (DD / 2)];
__device__ float g_xn[NB * NS];
__device__ float g_yn[NB * NS];

// ===========================================================================
// Stage 0: fp32 -> bf16 pack + row norms. One warp per row (X and Y).
// ===========================================================================
__global__ void __launch_bounds__(256)
convert_kernel(const float* __restrict__ X, const float* __restrict__ Y) {
    const int gw = blockIdx.x * 8 + (threadIdx.x >> 5);   // 0 .. 65535
    const int lane = threadIdx.x & 31;
    const bool isY = gw >= NB * NS;
    const int row = isY ? gw - NB * NS : gw;              // b*NS + r
    const float* src = (isY ? Y : X) + (size_t)row * DD;

    float2 v = reinterpret_cast<const float2*>(src)[lane];
    float s = v.x * v.x + v.y * v.y;
#pragma unroll
    for (int off = 16; off > 0; off >>= 1)
        s += __shfl_xor_sync(0xffffffffu, s, off);

    __nv_bfloat162 h = __floats2bfloat162_rn(v.x, v.y);
    uint32_t pk = *reinterpret_cast<uint32_t*>(&h);
    (isY ? g_Ybf : g_Xbf)[(size_t)row * 32 + lane] = pk;
    if (lane == 0) (isY ? g_yn : g_xn)[row] = s;
}

// ===========================================================================
// Stage 1: bf16 HMMA cdist. C = X.Y^T via mma.sync m16n8k16 (baseline PTX),
// fragments loaded straight from L2-resident bf16 arrays; fused
// E = exp(-sqrt(max(0, xn + yn - 2C))) epilogue.
// Grid (4,4,64), 256 thr = 8 warps: warp w -> (mw = w&3)*32 rows,
// (nw = w>>2)*64 cols of a 128x128 tile. Per warp: 2 m-tiles x 8 n-tiles.
// ===========================================================================
__global__ void __launch_bounds__(256)
cdist_mma(int dummy) {
    const int b  = blockIdx.z;
    const int i0 = blockIdx.y * 128;
    const int j0 = blockIdx.x * 128;
    const int tid = threadIdx.x;
    const int w = tid >> 5, lane = tid & 31;
    const int mw = w & 3, nw = w >> 2;
    const int g = lane >> 2, t = lane & 3;

    const uint32_t* Xu = g_Xbf + ((size_t)b * NS + i0) * 32;
    const uint32_t* Yu = g_Ybf + ((size_t)b * NS + j0) * 32;

    float acc[2][8][4];
#pragma unroll
    for (int mt = 0; mt < 2; ++mt)
#pragma unroll
        for (int nt = 0; nt < 8; ++nt)
#pragma unroll
            for (int q = 0; q < 4; ++q) acc[mt][nt][q] = 0.0f;

    const int rA = mw * 32 + g;     // a0 row (local)
    const int rB = nw * 64 + g;     // b0 col base (local), + nt*8

#pragma unroll
    for (int ks = 0; ks < 4; ++ks) {
        const int kb = ks * 8;      // u32 offset of this k-step (16 bf16)
        uint32_t a[2][4];
#pragma unroll
        for (int mt = 0; mt < 2; ++mt) {
            const uint32_t* p = Xu + (size_t)(rA + mt * 16) * 32 + kb + t;
            a[mt][0] = p[0];
            a[mt][1] = p[8 * 32];
            a[mt][2] = p[4];
            a[mt][3] = p[8 * 32 + 4];
        }
#pragma unroll
        for (int nt = 0; nt < 8; ++nt) {
            const uint32_t* q = Yu + (size_t)(rB + nt * 8) * 32 + kb + t;
            uint32_t b0 = q[0], b1 = q[4];
#pragma unroll
            for (int mt = 0; mt < 2; ++mt) {
                asm volatile(
                    "mma.sync.aligned.m16n8k16.row.col.f32.bf16.bf16.f32 "
                    "{%0,%1,%2,%3}, {%4,%5,%6,%7}, {%8,%9}, {%0,%1,%2,%3};"
                    : "+f"(acc[mt][nt][0]), "+f"(acc[mt][nt][1]),
                      "+f"(acc[mt][nt][2]), "+f"(acc[mt][nt][3])
                    : "r"(a[mt][0]), "r"(a[mt][1]),
                      "r"(a[mt][2]), "r"(a[mt][3]),
                      "r"(b0), "r"(b1));
            }
        }
    }

    // Epilogue. C frag: {c0,c1} at (row g, cols 2t,2t+1); {c2,c3} at row g+8.
    const float* xnp = g_xn + b * NS + i0;
    const float* ynp = g_yn + b * NS + j0;
#pragma unroll
    for (int mt = 0; mt < 2; ++mt) {
        const int r0 = mw * 32 + mt * 16 + g;
        const int r1 = r0 + 8;
        const float xn0 = xnp[r0], xn1 = xnp[r1];
        float* e0 = g_Ebuf + PADF + ((size_t)b * NS + i0 + r0) * NS + j0;
        float* e1 = g_Ebuf + PADF + ((size_t)b * NS + i0 + r1) * NS + j0;
#pragma unroll
        for (int nt = 0; nt < 8; ++nt) {
            const int c0 = nw * 64 + nt * 8 + 2 * t;
            const float2 yn2 = *reinterpret_cast<const float2*>(ynp + c0);
            float d2; float2 o;
            d2 = xn0 + yn2.x - 2.0f * acc[mt][nt][0];
            o.x = exp2f(-L2E * sqrtf(fmaxf(d2, 0.0f)));
            d2 = xn0 + yn2.y - 2.0f * acc[mt][nt][1];
            o.y = exp2f(-L2E * sqrtf(fmaxf(d2, 0.0f)));
            *reinterpret_cast<float2*>(e0 + c0) = o;
            d2 = xn1 + yn2.x - 2.0f * acc[mt][nt][2];
            o.x = exp2f(-L2E * sqrtf(fmaxf(d2, 0.0f)));
            d2 = xn1 + yn2.y - 2.0f * acc[mt][nt][3];
            o.y = exp2f(-L2E * sqrtf(fmaxf(d2, 0.0f)));
            *reinterpret_cast<float2*>(e1 + c0) = o;
        }
    }
    (void)dummy;
}

// ===========================================================================
// Stage 2: weight-domain soft-DTW (R4 structure, de-clamped).
// Offset slot indexing: inactive reads hit pristine zero slots, inactive
// writes land in disjoint slot ranges -> zero clamps / act-selects.
// ===========================================================================
__device__ __forceinline__ float exp2i_neg(int e) {
    return (e >= -126) ? __int_as_float((e + 127) << 23) : 0.0f;
}

__device__ __forceinline__ void subtile4(
    float4 top, int sTop,
    float& cornE, int& cornC2,
    float (&left)[4], int& leftC2,
    float4 e0, float4 e1, float4 e2, float4 e3,
    float4& outB, int& outC2)
{
    int c2 = max(max(sTop, cornC2), leftC2);
    const float ft = exp2i_neg(sTop   - c2);
    const float fc = exp2i_neg(cornC2 - c2);
    const float fl = exp2i_neg(leftC2 - c2);

    float prev[5];
    prev[0] = cornE * fc;
    prev[1] = top.x * ft; prev[2] = top.y * ft;
    prev[3] = top.z * ft; prev[4] = top.w * ft;
    float lE[4] = {left[0] * fl, left[1] * fl, left[2] * fl, left[3] * fl};
    const float newCorn = prev[4];

    float4 dt[4] = {e0, e1, e2, e3};
    float right[4];
#pragma unroll
    for (int a = 0; a < 4; ++a) {
        const float dd0 = dt[a].x, dd1 = dt[a].y, dd2 = dt[a].z, dd3 = dt[a].w;
        float carry = prev[0];
        prev[0] = lE[a];
        float s;
        s = (carry + prev[1]) + prev[0]; carry = prev[1]; prev[1] = dd0 * s;
        s = (carry + prev[2]) + prev[1]; carry = prev[2]; prev[2] = dd1 * s;
        s = (carry + prev[3]) + prev[2]; carry = prev[3]; prev[3] = dd2 * s;
        s = (carry + prev[4]) + prev[3];                  prev[4] = dd3 * s;
        right[a] = prev[4];
    }

    // Row group renorm (bit-trick rs = 2^-em).
    {
        float mr = fmaxf(fmaxf(prev[1], prev[2]), fmaxf(prev[3], prev[4]));
        int mb = __float_as_int(mr);
        float rsr = __int_as_float(0x7F000000 - (mb & 0x7f800000));
        int emr = ((mb >> 23) & 0xff) - 127;
        outB = make_float4(prev[1] * rsr, prev[2] * rsr,
                           prev[3] * rsr, prev[4] * rsr);
        outC2 = (mr > 0.0f) ? (c2 + emr) : C2_NEG;
    }
    // Column group renorm -> next tile's left frontier.
    {
        float mc = fmaxf(fmaxf(right[0], right[1]), fmaxf(right[2], right[3]));
        int mb = __float_as_int(mc);
        float rsc = __int_as_float(0x7F000000 - (mb & 0x7f800000));
        int emc = ((mb >> 23) & 0xff) - 127;
        left[0] = right[0] * rsc; left[1] = right[1] * rsc;
        left[2] = right[2] * rsc; left[3] = right[3] * rsc;
        leftC2 = (mc > 0.0f) ? (c2 + emc) : C2_NEG;
    }
    // Corner: own-exponent renorm (scale must track magnitude).
    {
        int nb = __float_as_int(newCorn);
        cornE  = newCorn * __int_as_float(0x7F000000 - (nb & 0x7f800000));
        cornC2 = (newCorn > 0.0f) ? (c2 + (((nb >> 23) & 0xff) - 127)) : C2_NEG;
    }
}

__device__ __forceinline__ void dp_step(
    int kd, int ti, const float* __restrict__ pf,
    const float4 (&cb)[8], float4 (&nb)[8],
    float4 (*rowE4)[SLOTS], int (*rowC2s)[SLOTS],
    float (&left)[4], int& leftC2, float& cornE, int& cornC2)
{
    const int tj = kd - ti;
    const int wb = kd & 1, rb = wb ^ 1;
    const int ix = 2 * tj + SLOT_OFF;

    float4 t0 = rowE4[rb][ix];
    float4 t1 = rowE4[rb][ix + 1];
    int s0 = rowC2s[rb][ix];
    int s1 = rowC2s[rb][ix + 1];

    if (tj == 0) {   // activation reset (predicated)
        left[0] = left[1] = left[2] = left[3] = 0.0f;
        leftC2 = C2_NEG;
        cornE  = (ti == 0) ? 1.0f : 0.0f;
        cornC2 = (ti == 0) ? 0 : C2_NEG;
    }

    // Prefetch next tile (guard-padded: no clamps, marching pointer).
#pragma unroll
    for (int a = 0; a < 4; ++a) {
        nb[2 * a]     = *reinterpret_cast<const float4*>(pf + a * NS);
        nb[2 * a + 1] = *reinterpret_cast<const float4*>(pf + a * NS + 4);
    }

    float4 b0, b1; int c0, c1;
    subtile4(t0, s0, cornE, cornC2, left, leftC2, cb[0], cb[2], cb[4], cb[6], b0, c0);
    subtile4(t1, s1, cornE, cornC2, left, leftC2, cb[1], cb[3], cb[5], cb[7], b1, c1);

    rowE4[wb][ix]      = b0;
    rowE4[wb][ix + 1]  = b1;
    rowC2s[wb][ix]     = c0;
    rowC2s[wb][ix + 1] = c1;
    __syncthreads();
}

__global__ void __launch_bounds__(128, 1)
dp_kernel(float* __restrict__ out) {
    const int b = blockIdx.x;
    const float* Eb = g_Ebuf + PADF + (size_t)b * NS * NS;

    __shared__ __align__(16) float4 rowE4[2][SLOTS];
    __shared__ int rowC2s[2][SLOTS];

    const int ti = threadIdx.x;
    const float* Erow0 = Eb + (size_t)(ti * 4) * NS;

    // Pre-zero ALL slots of both parities (boundary + inactive reads).
    {
        float4 z = make_float4(0.f, 0.f, 0.f, 0.f);
        float4* re = &rowE4[0][0];
        for (int s = ti; s < 2 * SLOTS; s += 128) re[s] = z;
        int* rc = &rowC2s[0][0];
        for (int s = ti; s < 2 * SLOTS; s += 128) rc[s] = C2_NEG;
    }

    float4 bufA[8], bufB[8];
#pragma unroll
    for (int a = 0; a < 4; ++a) {   // preload tile tj=0 (ti=0 consumes at kd=0)
        bufA[2 * a]     = *reinterpret_cast<const float4*>(Erow0 + a * NS);
        bufA[2 * a + 1] = *reinterpret_cast<const float4*>(Erow0 + a * NS + 4);
    }
#pragma unroll
    for (int a = 0; a < 8; ++a) bufB[a] = bufA[a];

    float left[4] = {0.f, 0.f, 0.f, 0.f};
    int leftC2 = C2_NEG;
    float cornE = 0.f;
    int cornC2 = C2_NEG;

    __syncthreads();

    const float* pf = Erow0 + (1 - ti) * 8;   // column (kd - ti + 1)*8 at kd=0
    for (int kd = 0; kd < NDIAG; kd += 2) {
        dp_step(kd,     ti, pf,     bufA, bufB, rowE4, rowC2s,
                left, leftC2, cornE, cornC2);
        dp_step(kd + 1, ti, pf + 8, bufB, bufA, rowE4, rowC2s,
                left, leftC2, cornE, cornC2);
        pf += 16;
    }

    // Thread 127 wrote tile (127,63) at kd=190 (parity 0), slot 2*63+OFF+1.
    if (ti == 0) {
        const int fx = 2 * (GTJ - 1) + SLOT_OFF + 1;
        float e  = fmaxf(rowE4[0][fx].w, 1.17549435e-38f);
        float c2 = (float)rowC2s[0][fx];
        out[b] = -(log2f(e) + c2) * 0.69314718055994530942f;
    }
}

// ---------------------------------------------------------------------------
extern "C" void kernel_launch(void* const* d_in, const int* in_sizes, int n_in,
                              void* d_out, int out_size) {
    (void)in_sizes; (void)n_in; (void)out_size;
    const float* X = (const float*)d_in[0];
    const float* Y = (const float*)d_in[1];
    float* out = (float*)d_out;

    convert_kernel<<<NB * NS * 2 / 8, 256>>>(X, Y);   // 8192 blocks

    dim3 g1(NS / 128, NS / 128, NB);   // (4, 4, 64)
    cdist_mma<<<g1, 256>>>(0);

    dp_kernel<<<NB, 128>>>(out);
}